// round 10
// baseline (speedup 1.0000x reference)
#include <cuda_runtime.h>
#include <math.h>

#define BB 4
#define TT 128
#define HH 1024
#define EE 512
#define AA 512
#define VV 16000
#define SS 512
#define NB 128
#define NT 512
#define DSMEM (48*1024*4)

// ---------------- persistent device state ----------------
__device__ __align__(16) float d_h[2][BB][HH];
__device__ __align__(16) float d_av[2][BB][AA];
__device__ __align__(16) float d_enc_out[BB][TT][HH];
__device__ __align__(16) float d_P[BB][AA][TT];
__device__ __align__(16) float d_gi[TT][BB][3*HH];
__device__ float d_score[BB][TT];
__device__ float d_cval[NB][BB];
__device__ int   d_cidx[NB][BB];
__device__ unsigned d_gcnt[8*64];   // group counters, 256B apart
__device__ unsigned d_rcnt;
__device__ unsigned d_gen2;

__device__ __forceinline__ float wred(float v){
    #pragma unroll
    for (int o = 16; o; o >>= 1) v += __shfl_down_sync(0xffffffffu, v, o);
    return v;
}
__device__ __forceinline__ float sigm(float x){ return 1.0f / (1.0f + expf(-x)); }

// hierarchical acquire/release grid barrier: 8 groups x 16 blocks + root
__device__ __forceinline__ void gbar(int bl){
    __syncthreads();
    if (threadIdx.x == 0){
        unsigned gen;
        asm volatile("ld.acquire.gpu.u32 %0, [%1];" : "=r"(gen) : "l"(&d_gen2) : "memory");
        unsigned old;
        unsigned* gc = &d_gcnt[(bl >> 4) * 64];
        asm volatile("atom.acq_rel.gpu.add.u32 %0, [%1], 1;" : "=r"(old) : "l"(gc) : "memory");
        if (old == 15u){
            unsigned ro;
            asm volatile("atom.acq_rel.gpu.add.u32 %0, [%1], 1;" : "=r"(ro) : "l"(&d_rcnt) : "memory");
            if (ro == 7u){
                #pragma unroll
                for (int i = 0; i < 8; i++) d_gcnt[i*64] = 0u;
                d_rcnt = 0u;
                asm volatile("st.release.gpu.u32 [%0], %1;" :: "l"(&d_gen2), "r"(gen + 1u) : "memory");
            }
        }
        unsigned g2;
        do {
            asm volatile("ld.acquire.gpu.u32 %0, [%1];" : "=r"(g2) : "l"(&d_gen2) : "memory");
        } while (g2 == gen);
    }
    __syncthreads();
}

// Whh row-dot for next step's gates (SMEM weights x SMEM h)
__device__ __forceinline__ void predot_hh(int d, int j0, const float* sWhh, const float* sm_hst,
                                          float* sm_phh, const float* bhh, int lane){
    int jl = d/3, g = d%3, row = g*HH + j0 + jl;
    const float4* Wr = (const float4*)(sWhh + d*HH);
    float a[BB] = {0.f,0.f,0.f,0.f};
    #pragma unroll
    for (int i = 0; i < 8; i++){
        int k4 = lane + 32*i;
        float4 wv = Wr[k4];
        #pragma unroll
        for (int b = 0; b < BB; b++){
            float4 hv = ((const float4*)(sm_hst + b*HH))[k4];
            a[b] += wv.x*hv.x + wv.y*hv.y + wv.z*hv.z + wv.w*hv.w;
        }
    }
    #pragma unroll
    for (int b = 0; b < BB; b++){
        float r = wred(a[b]);
        if (lane == 0) sm_phh[d*BB + b] = r + bhh[row];
    }
}

// Wih(av columns) row-dot for next step's gates
__device__ __forceinline__ void predot_av(int d, int j0, const float* sWih, const float* sm_av,
                                          float* sm_pia, const float* bih, int lane){
    int jl = d/3, g = d%3, row = g*HH + j0 + jl;
    const float4* Wr = (const float4*)(sWih + d*HH + EE);
    float a[BB] = {0.f,0.f,0.f,0.f};
    #pragma unroll
    for (int i = 0; i < 4; i++){
        int k4 = lane + 32*i;
        float4 wv = Wr[k4];
        #pragma unroll
        for (int b = 0; b < BB; b++){
            float4 av = ((const float4*)(sm_av + b*AA))[k4];
            a[b] += wv.x*av.x + wv.y*av.y + wv.z*av.z + wv.w*av.w;
        }
    }
    #pragma unroll
    for (int b = 0; b < BB; b++){
        float r = wred(a[b]);
        if (lane == 0) sm_pia[d*BB + b] = r + bih[row];
    }
}

__global__ __launch_bounds__(NT, 1) void seq2seq_kernel(
    const int*   __restrict__ inputs,
    const float* __restrict__ enc_emb, const float* __restrict__ enc_Wih,
    const float* __restrict__ enc_Whh, const float* __restrict__ enc_bih,
    const float* __restrict__ enc_bhh,
    const float* __restrict__ dec_emb, const float* __restrict__ dec_Wih,
    const float* __restrict__ dec_Whh, const float* __restrict__ dec_bih,
    const float* __restrict__ dec_bhh,
    const float* __restrict__ W_av,  const float* __restrict__ b_av,
    const float* __restrict__ W_cls, const float* __restrict__ b_cls,
    float* __restrict__ out)
{
    extern __shared__ __align__(16) float dyn[];
    float* sWih = dyn;              // 24x1024 (decoder phase)
    float* sWhh = dyn + 24*HH;      // 24x1024 (enc rows during encoder, then dec rows)

    __shared__ __align__(16) float sm_av[BB*AA];    // 8 KB
    __shared__ __align__(16) float sm_hst[BB*HH];   // 16 KB
    __shared__ float sm_w[BB*TT];
    __shared__ float sm_lg[BB*125];
    __shared__ float sm_ge[24*BB];
    __shared__ float sm_phh[24*BB];
    __shared__ float sm_pia[24*BB];
    __shared__ float sm_bv[16*BB];
    __shared__ int   sm_bi[16*BB];
    __shared__ float sm_part[16];
    __shared__ int   sm_ids[BB];

    const int tid  = threadIdx.x;
    const int bl   = blockIdx.x;
    const int w    = tid >> 5;
    const int lane = tid & 31;
    const int j0   = bl * 8;

    // ---- zero recurrent state (replay determinism) ----
    for (int i = bl*NT + tid; i < 2*BB*HH + 2*BB*AA; i += NB*NT){
        if (i < 2*BB*HH) (&d_h[0][0][0])[i] = 0.f;
        else             (&d_av[0][0][0])[i - 2*BB*HH] = 0.f;
    }

    // ---- load this block's 24 enc_Whh rows to SMEM ----
    for (int i = tid; i < 24*HH; i += NT){
        int d = i >> 10, k = i & 1023;
        int jl = d/3, g = d%3;
        sWhh[i] = enc_Whh[(size_t)(g*HH + j0 + jl)*HH + k];
    }

    // ---- setup A: encoder input-gate preactivations gi[t][b][row] ----
    {
        int r0 = bl * 24;
        if (w < 12){
            int row0 = r0 + 2*w, row1 = row0 + 1;
            float w0[16], w1[16];
            #pragma unroll
            for (int i = 0; i < 16; i++){
                w0[i] = enc_Wih[row0*EE + lane + 32*i];
                w1[i] = enc_Wih[row1*EE + lane + 32*i];
            }
            float b0 = enc_bih[row0], b1 = enc_bih[row1];
            for (int tb = 0; tb < TT*BB; tb++){
                int t = tb >> 2, b = tb & 3;
                int tok = inputs[b*TT + t];
                const float* em = enc_emb + (size_t)tok * EE;
                float a0 = 0.f, a1 = 0.f;
                #pragma unroll
                for (int i = 0; i < 16; i++){
                    float e = em[lane + 32*i];
                    a0 += w0[i]*e; a1 += w1[i]*e;
                }
                a0 = wred(a0); a1 = wred(a1);
                if (lane == 0){
                    d_gi[t][b][row0] = a0 + b0;
                    d_gi[t][b][row1] = a1 + b1;
                }
            }
        }
    }
    gbar(bl);

    // ---- encoder scan (SMEM weights) ----
    for (int t = 0; t < TT; t++){
        int cur = t & 1, nxt = cur ^ 1;
        for (int d = w; d < 24; d += 16){
            int jl = d/3, g = d%3;
            int row = g*HH + j0 + jl;
            const float4* Wr = (const float4*)(sWhh + d*HH);
            float a[BB] = {0.f,0.f,0.f,0.f};
            #pragma unroll
            for (int i = 0; i < 8; i++){
                int k4 = lane + 32*i;
                float4 wv = Wr[k4];
                #pragma unroll
                for (int b = 0; b < BB; b++){
                    float4 hv = ((const float4*)d_h[cur][b])[k4];
                    a[b] += wv.x*hv.x + wv.y*hv.y + wv.z*hv.z + wv.w*hv.w;
                }
            }
            #pragma unroll
            for (int b = 0; b < BB; b++){
                float r = wred(a[b]);
                if (lane == 0) sm_ge[d*BB + b] = r + enc_bhh[row];
            }
        }
        __syncthreads();
        if (tid < 32){
            int jl = tid >> 2, b = tid & 3, j = j0 + jl;
            float gr = sm_ge[(jl*3+0)*BB+b], gz = sm_ge[(jl*3+1)*BB+b], gn = sm_ge[(jl*3+2)*BB+b];
            float ir = d_gi[t][b][j], iz = d_gi[t][b][j+HH], inn = d_gi[t][b][j+2*HH];
            float r = sigm(ir + gr), z = sigm(iz + gz);
            float n = tanhf(inn + r*gn);
            float hp = d_h[cur][b][j];
            float hn = (1.f - z)*n + z*hp;
            d_h[nxt][b][j]     = hn;
            d_enc_out[b][t][j] = hn;
        }
        gbar(bl);
    }

    // ---- setup P: P[b][a][t] = W_av_left[a] . enc_out[b][t] ----
    {
        int a = bl*4 + (w & 3);
        int q = w >> 2;
        float wa[32];
        #pragma unroll
        for (int i = 0; i < 32; i++) wa[i] = W_av[(size_t)a*2*HH + lane + 32*i];
        for (int tb = q*128; tb < q*128 + 128; tb++){
            int t = tb >> 2, b = tb & 3;
            const float* eo = d_enc_out[b][t];
            float acc = 0.f;
            #pragma unroll
            for (int i = 0; i < 32; i++) acc += wa[i] * eo[lane + 32*i];
            acc = wred(acc);
            if (lane == 0) d_P[b][a][t] = acc;
        }
    }
    gbar(bl);

    // ---- load decoder weight rows to SMEM (overwrite encoder rows) ----
    for (int i = tid; i < 24*HH; i += NT){
        int d = i >> 10, k = i & 1023;
        int jl = d/3, g = d%3;
        size_t row = (size_t)(g*HH + j0 + jl);
        sWih[i] = dec_Wih[row*(size_t)(EE+AA) + k];
        sWhh[i] = dec_Whh[row*(size_t)HH + k];
    }
    // stage enc-final h and av0, compute pre-dots for step 0
    for (int i = tid; i < BB*HH/4; i += NT) ((float4*)sm_hst)[i] = ((const float4*)(&d_h[0][0][0]))[i];
    for (int i = tid; i < BB*AA/4; i += NT) ((float4*)sm_av)[i]  = ((const float4*)(&d_av[0][0][0]))[i];
    __syncthreads();
    for (int d = w; d < 24; d += 16){
        predot_hh(d, j0, sWhh, sm_hst, sm_phh, dec_bhh, lane);
        predot_av(d, j0, sWih, sm_av,  sm_pia, dec_bih, lane);
    }

    // ---- decoder: 512 greedy steps ----
    const int base_v = bl * 125;
    const size_t OUT_ATT = (size_t)SS * BB * VV;

    for (int s = 0; s < SS; s++){
        int cur = s & 1, nxt = cur ^ 1;

        // combine previous step's per-block argmax candidates -> ids
        if (w < BB){
            int b = w;
            float best = -3.4e38f; int bi = 0;
            if (s > 0){
                #pragma unroll
                for (int i = 0; i < 4; i++){
                    int q2 = lane + 32*i;
                    float v = d_cval[q2][b]; int ii = d_cidx[q2][b];
                    if (v > best || (v == best && ii < bi)){ best = v; bi = ii; }
                }
                #pragma unroll
                for (int o = 16; o; o >>= 1){
                    float ov = __shfl_xor_sync(0xffffffffu, best, o);
                    int   oi = __shfl_xor_sync(0xffffffffu, bi,   o);
                    if (ov > best || (ov == best && oi < bi)){ best = ov; bi = oi; }
                }
            }
            if (lane == 0) sm_ids[b] = (s > 0) ? bi : 0;
        }
        __syncthreads();

        // ---- phase A: emb-dot + gate combine (Whh/av parts precomputed) ----
        for (int d = w; d < 24; d += 16){
            const float4* Wr = (const float4*)(sWih + d*HH);  // emb columns
            const float4* em[BB];
            #pragma unroll
            for (int b = 0; b < BB; b++)
                em[b] = (const float4*)(dec_emb + (size_t)sm_ids[b] * EE);
            float a[BB] = {0.f,0.f,0.f,0.f};
            #pragma unroll
            for (int i = 0; i < 4; i++){
                int k4 = lane + 32*i;
                float4 wv = Wr[k4];
                #pragma unroll
                for (int b = 0; b < BB; b++){
                    float4 xv = em[b][k4];
                    a[b] += wv.x*xv.x + wv.y*xv.y + wv.z*xv.z + wv.w*xv.w;
                }
            }
            #pragma unroll
            for (int b = 0; b < BB; b++){
                float r = wred(a[b]);
                if (lane == 0) sm_ge[d*BB + b] = r;
            }
        }
        __syncthreads();
        if (tid < 32){
            int jl = tid >> 2, b = tid & 3, j = j0 + jl;
            float ir  = sm_ge[(jl*3+0)*BB+b] + sm_pia[(jl*3+0)*BB+b];
            float iz  = sm_ge[(jl*3+1)*BB+b] + sm_pia[(jl*3+1)*BB+b];
            float inn = sm_ge[(jl*3+2)*BB+b] + sm_pia[(jl*3+2)*BB+b];
            float gr  = sm_phh[(jl*3+0)*BB+b];
            float gz  = sm_phh[(jl*3+1)*BB+b];
            float gn  = sm_phh[(jl*3+2)*BB+b];
            float r = sigm(ir + gr), z = sigm(iz + gz);
            float n = tanhf(inn + r*gn);
            float hp = d_h[cur][b][j];
            d_h[nxt][b][j] = (1.f - z)*n + z*hp;
        }
        gbar(bl);

        // ---- phase B1: attention scores ----
        {
            int q2 = w >> 2, sub = w & 3;
            int idx = bl*4 + q2;
            int b = idx >> 7, t = idx & 127;
            const float4* eo = (const float4*)d_enc_out[b][t];
            const float4* hv = (const float4*)d_h[nxt][b];
            float acc = 0.f;
            #pragma unroll
            for (int i = 0; i < 2; i++){
                int k4 = sub*64 + lane + 32*i;
                float4 a4 = eo[k4], b4 = hv[k4];
                acc += a4.x*b4.x + a4.y*b4.y + a4.z*b4.z + a4.w*b4.w;
            }
            acc = wred(acc);
            if (lane == 0) sm_part[w] = acc;
            __syncthreads();
            if (tid < 4){
                int idx2 = bl*4 + tid;
                int b2 = idx2 >> 7, t2 = idx2 & 127;
                float sc = sm_part[tid*4+0] + sm_part[tid*4+1] + sm_part[tid*4+2] + sm_part[tid*4+3];
                if (inputs[b2*TT + t2] == 0) sc = -1e30f;
                d_score[b2][t2] = sc;
            }
        }
        gbar(bl);

        // ---- phase B2: softmax + attn_vec ----
        {
            if (w < 4){
                int b = w;
                float x[4];
                float m = -1e30f;
                #pragma unroll
                for (int i = 0; i < 4; i++){ x[i] = d_score[b][lane + 32*i]; m = fmaxf(m, x[i]); }
                #pragma unroll
                for (int o = 16; o; o >>= 1) m = fmaxf(m, __shfl_xor_sync(0xffffffffu, m, o));
                float sum = 0.f;
                #pragma unroll
                for (int i = 0; i < 4; i++){ x[i] = expf(x[i] - m); sum += x[i]; }
                #pragma unroll
                for (int o = 16; o; o >>= 1) sum += __shfl_xor_sync(0xffffffffu, sum, o);
                float inv = 1.f / sum;
                #pragma unroll
                for (int i = 0; i < 4; i++) sm_w[b*TT + lane + 32*i] = x[i] * inv;
            }
            __syncthreads();
            {
                int b = w & 3, a = bl*4 + (w >> 2);
                float acc = 0.f;
                #pragma unroll
                for (int i = 0; i < 4; i++){
                    int t = lane + 32*i;
                    acc += sm_w[b*TT + t] * d_P[b][a][t];
                }
                const float4* Wr = (const float4*)(W_av + (size_t)a*2*HH + HH);
                const float4* hv = (const float4*)d_h[nxt][b];
                #pragma unroll
                for (int i = 0; i < 8; i++){
                    int k4 = lane + 32*i;
                    float4 wv = Wr[k4]; float4 h4 = hv[k4];
                    acc += wv.x*h4.x + wv.y*h4.y + wv.z*h4.z + wv.w*h4.w;
                }
                acc = wred(acc);
                if (lane == 0) d_av[nxt][b][a] = tanhf(acc + b_av[a]);
            }
            if (bl < BB && tid < TT)
                out[OUT_ATT + ((size_t)s*BB + bl)*TT + tid] = sm_w[bl*TT + tid];
        }
        gbar(bl);

        // ---- phase C: logits + argmax + pre-dots for next step ----
        {
            for (int i = tid; i < BB*AA/4; i += NT) ((float4*)sm_av)[i]  = ((const float4*)(&d_av[nxt][0][0]))[i];
            for (int i = tid; i < BB*HH/4; i += NT) ((float4*)sm_hst)[i] = ((const float4*)(&d_h[nxt][0][0]))[i];
            __syncthreads();
            float bestv[BB] = {-3.4e38f,-3.4e38f,-3.4e38f,-3.4e38f};
            int   besti[BB] = {0,0,0,0};
            for (int u = w; u < 173; u += 16){
                if (u < 125){
                    int v = base_v + u;
                    const float4* Wr = (const float4*)(W_cls + (size_t)v * AA);
                    float a[BB] = {0.f,0.f,0.f,0.f};
                    #pragma unroll
                    for (int i = 0; i < 4; i++){
                        int k4 = lane + 32*i;
                        float4 wv = Wr[k4];
                        #pragma unroll
                        for (int b = 0; b < BB; b++){
                            float4 av4 = ((const float4*)(sm_av + b*AA))[k4];
                            a[b] += wv.x*av4.x + wv.y*av4.y + wv.z*av4.z + wv.w*av4.w;
                        }
                    }
                    #pragma unroll
                    for (int b = 0; b < BB; b++){
                        float lg = wred(a[b]);
                        if (lane == 0){
                            lg += b_cls[v];
                            sm_lg[b*125 + u] = lg;
                            if (lg > bestv[b]){ bestv[b] = lg; besti[b] = v; }
                        }
                    }
                } else if (u < 149){
                    predot_hh(u - 125, j0, sWhh, sm_hst, sm_phh, dec_bhh, lane);
                } else {
                    predot_av(u - 149, j0, sWih, sm_av,  sm_pia, dec_bih, lane);
                }
            }
            if (lane == 0){
                #pragma unroll
                for (int b = 0; b < BB; b++){ sm_bv[w*BB + b] = bestv[b]; sm_bi[w*BB + b] = besti[b]; }
            }
            __syncthreads();
            for (int i = tid; i < BB*125; i += NT){
                int b = i / 125, r = i % 125;
                out[((size_t)s*BB + b)*VV + base_v + r] = sm_lg[i];
            }
            if (tid < BB){
                int b = tid;
                float best = -3.4e38f; int bi = 0;
                for (int w2 = 0; w2 < 16; w2++){
                    float v = sm_bv[w2*BB + b]; int i2 = sm_bi[w2*BB + b];
                    if (v > best || (v == best && i2 < bi)){ best = v; bi = i2; }
                }
                d_cval[bl][b] = best; d_cidx[bl][b] = bi;
            }
        }
        gbar(bl);
    }
}

extern "C" void kernel_launch(void* const* d_in, const int* in_sizes, int n_in,
                              void* d_out, int out_size)
{
    (void)in_sizes; (void)n_in; (void)out_size;
    cudaFuncSetAttribute(seq2seq_kernel, cudaFuncAttributeMaxDynamicSharedMemorySize, DSMEM);
    seq2seq_kernel<<<NB, NT, DSMEM>>>(
        (const int*)  d_in[0],
        (const float*)d_in[1],  (const float*)d_in[2],  (const float*)d_in[3],
        (const float*)d_in[4],  (const float*)d_in[5],
        (const float*)d_in[6],  (const float*)d_in[7],  (const float*)d_in[8],
        (const float*)d_in[9],  (const float*)d_in[10],
        (const float*)d_in[11], (const float*)d_in[12],
        (const float*)d_in[13], (const float*)d_in[14],
        (float*)d_out);
}

// round 11
// speedup vs baseline: 1.1947x; 1.1947x over previous
#include <cuda_runtime.h>
#include <math.h>

#define BB 4
#define TT 128
#define HH 1024
#define EE 512
#define AA 512
#define VV 16000
#define SS 512
#define NB 128
#define NT 512
#define DSMEM (48*1024*4)
#define SCALE 1073741824.0f
#define INV_SCALE 9.313225746154785e-10f

// ---------------- persistent device state ----------------
__device__ __align__(16) float d_h[2][BB][HH];
__device__ __align__(16) float d_av[2][BB][AA];
__device__ __align__(16) float d_enc_out[BB][TT][HH];
__device__ __align__(16) float d_P[BB][AA][TT];
__device__ __align__(16) float d_gi[TT][BB][3*HH];
__device__ unsigned long long d_score_i[BB*TT];
__device__ float d_cval[NB][BB];
__device__ int   d_cidx[NB][BB];
__device__ unsigned d_cnt2;
__device__ unsigned d_flag[NB*64];   // one flag per block, 256B apart

__device__ __forceinline__ float wred(float v){
    #pragma unroll
    for (int o = 16; o; o >>= 1) v += __shfl_down_sync(0xffffffffu, v, o);
    return v;
}
__device__ __forceinline__ float sigm(float x){ return 1.0f / (1.0f + expf(-x)); }

// grid barrier: single arrival counter + per-block release flags (warp fan-out)
__device__ __forceinline__ void gbar(int bl, unsigned gen){
    __syncthreads();
    if (threadIdx.x < 32){
        int lane = threadIdx.x;
        unsigned old = 0u;
        if (lane == 0)
            asm volatile("atom.acq_rel.gpu.add.u32 %0, [%1], 1;" : "=r"(old) : "l"(&d_cnt2) : "memory");
        old = __shfl_sync(0xffffffffu, old, 0);
        if (old == (unsigned)(NB - 1)){
            if (lane == 0) d_cnt2 = 0u;
            __syncwarp();
            asm volatile("fence.acq_rel.gpu;" ::: "memory");
            #pragma unroll
            for (int i = 0; i < 4; i++)
                asm volatile("st.relaxed.gpu.u32 [%0], %1;"
                             :: "l"(&d_flag[(lane*4 + i)*64]), "r"(gen) : "memory");
        }
        if (lane == 0){
            unsigned f;
            do {
                asm volatile("ld.acquire.gpu.u32 %0, [%1];" : "=r"(f) : "l"(&d_flag[bl*64]) : "memory");
            } while (f != gen);
        }
    }
    __syncthreads();
}

__global__ __launch_bounds__(NT, 1) void seq2seq_kernel(
    const int*   __restrict__ inputs,
    const float* __restrict__ enc_emb, const float* __restrict__ enc_Wih,
    const float* __restrict__ enc_Whh, const float* __restrict__ enc_bih,
    const float* __restrict__ enc_bhh,
    const float* __restrict__ dec_emb, const float* __restrict__ dec_Wih,
    const float* __restrict__ dec_Whh, const float* __restrict__ dec_bih,
    const float* __restrict__ dec_bhh,
    const float* __restrict__ W_av,  const float* __restrict__ b_av,
    const float* __restrict__ W_cls, const float* __restrict__ b_cls,
    float* __restrict__ out)
{
    extern __shared__ __align__(16) float dyn[];
    float* sWih = dyn;              // 24x1024 decoder ih rows (x = [emb;av], 1024 wide)
    float* sWhh = dyn + 24*HH;      // 24x1024 (enc rows during encoder, then dec hh rows)

    __shared__ __align__(16) float sm_av[BB*AA];    // 8 KB
    __shared__ float sm_w[BB*TT];
    __shared__ float sm_lg[BB*125];
    __shared__ float sm_ge[48*BB];
    __shared__ float sm_hloc[8*BB];
    __shared__ float sm_bv[16*BB];
    __shared__ int   sm_bi[16*BB];
    __shared__ int   sm_ids[BB];

    const int tid  = threadIdx.x;
    const int bl   = blockIdx.x;
    const int w    = tid >> 5;
    const int lane = tid & 31;
    const int j0   = bl * 8;
    unsigned bgen = 0;

    // reset own barrier flag (state persists across graph replays)
    if (tid == 0) d_flag[bl*64] = 0u;

    // ---- zero recurrent state (replay determinism) ----
    for (int i = bl*NT + tid; i < 2*BB*HH + 2*BB*AA; i += NB*NT){
        if (i < 2*BB*HH) (&d_h[0][0][0])[i] = 0.f;
        else             (&d_av[0][0][0])[i - 2*BB*HH] = 0.f;
    }

    // ---- load this block's 24 enc_Whh rows to SMEM ----
    for (int i = tid; i < 24*HH; i += NT){
        int d = i >> 10, k = i & 1023;
        int jl = d/3, g = d%3;
        sWhh[i] = enc_Whh[(size_t)(g*HH + j0 + jl)*HH + k];
    }

    // ---- setup A: encoder input-gate preactivations ----
    {
        int r0 = bl * 24;
        if (w < 12){
            int row0 = r0 + 2*w, row1 = row0 + 1;
            float w0[16], w1[16];
            #pragma unroll
            for (int i = 0; i < 16; i++){
                w0[i] = enc_Wih[row0*EE + lane + 32*i];
                w1[i] = enc_Wih[row1*EE + lane + 32*i];
            }
            float b0 = enc_bih[row0], b1 = enc_bih[row1];
            for (int tb = 0; tb < TT*BB; tb++){
                int t = tb >> 2, b = tb & 3;
                int tok = inputs[b*TT + t];
                const float* em = enc_emb + (size_t)tok * EE;
                float a0 = 0.f, a1 = 0.f;
                #pragma unroll
                for (int i = 0; i < 16; i++){
                    float e = em[lane + 32*i];
                    a0 += w0[i]*e; a1 += w1[i]*e;
                }
                a0 = wred(a0); a1 = wred(a1);
                if (lane == 0){
                    d_gi[t][b][row0] = a0 + b0;
                    d_gi[t][b][row1] = a1 + b1;
                }
            }
        }
    }
    gbar(bl, ++bgen);

    // ---- encoder scan (SMEM weights) ----
    for (int t = 0; t < TT; t++){
        int cur = t & 1, nxt = cur ^ 1;
        for (int d = w; d < 24; d += 16){
            int jl = d/3, g = d%3;
            int row = g*HH + j0 + jl;
            const float4* Wr = (const float4*)(sWhh + d*HH);
            float a[BB] = {0.f,0.f,0.f,0.f};
            #pragma unroll
            for (int i = 0; i < 8; i++){
                int k4 = lane + 32*i;
                float4 wv = Wr[k4];
                #pragma unroll
                for (int b = 0; b < BB; b++){
                    float4 hv = ((const float4*)d_h[cur][b])[k4];
                    a[b] += wv.x*hv.x + wv.y*hv.y + wv.z*hv.z + wv.w*hv.w;
                }
            }
            #pragma unroll
            for (int b = 0; b < BB; b++){
                float r = wred(a[b]);
                if (lane == 0) sm_ge[d*BB + b] = r + enc_bhh[row];
            }
        }
        __syncthreads();
        if (tid < 32){
            int jl = tid >> 2, b = tid & 3, j = j0 + jl;
            float gr = sm_ge[(jl*3+0)*BB+b], gz = sm_ge[(jl*3+1)*BB+b], gn = sm_ge[(jl*3+2)*BB+b];
            float ir = d_gi[t][b][j], iz = d_gi[t][b][j+HH], inn = d_gi[t][b][j+2*HH];
            float r = sigm(ir + gr), z = sigm(iz + gz);
            float n = tanhf(inn + r*gn);
            float hp = d_h[cur][b][j];
            float hn = (1.f - z)*n + z*hp;
            d_h[nxt][b][j]     = hn;
            d_enc_out[b][t][j] = hn;
        }
        gbar(bl, ++bgen);
    }

    // ---- setup P: P[b][a][t] = W_av_left[a] . enc_out[b][t] ----
    {
        int a = bl*4 + (w & 3);
        int q = w >> 2;
        float wa[32];
        #pragma unroll
        for (int i = 0; i < 32; i++) wa[i] = W_av[(size_t)a*2*HH + lane + 32*i];
        for (int tb = q*128; tb < q*128 + 128; tb++){
            int t = tb >> 2, b = tb & 3;
            const float* eo = d_enc_out[b][t];
            float acc = 0.f;
            #pragma unroll
            for (int i = 0; i < 32; i++) acc += wa[i] * eo[lane + 32*i];
            acc = wred(acc);
            if (lane == 0) d_P[b][a][t] = acc;
        }
    }
    // zero this block's score slots (also self-restored every step in phase C)
    if (tid < 4) d_score_i[bl*4 + tid] = 0ull;
    gbar(bl, ++bgen);

    // ---- load decoder weight rows to SMEM ----
    for (int i = tid; i < 24*HH; i += NT){
        int d = i >> 10, k = i & 1023;
        int jl = d/3, g = d%3;
        size_t row = (size_t)(g*HH + j0 + jl);
        sWih[i] = dec_Wih[row*(size_t)(EE+AA) + k];
        sWhh[i] = dec_Whh[row*(size_t)HH + k];
    }

    // ---- decoder: 512 greedy steps, 3 grid barriers each ----
    const int base_v = bl * 125;
    const size_t OUT_ATT = (size_t)SS * BB * VV;

    for (int s = 0; s < SS; s++){
        int cur = s & 1, nxt = cur ^ 1;

        // ids from previous step's per-block candidates
        if (w < BB){
            int b = w;
            float best = -3.4e38f; int bi = 0;
            if (s > 0){
                #pragma unroll
                for (int i = 0; i < 4; i++){
                    int q2 = lane + 32*i;
                    float v = d_cval[q2][b]; int ii = d_cidx[q2][b];
                    if (v > best || (v == best && ii < bi)){ best = v; bi = ii; }
                }
                #pragma unroll
                for (int o = 16; o; o >>= 1){
                    float ov = __shfl_xor_sync(0xffffffffu, best, o);
                    int   oi = __shfl_xor_sync(0xffffffffu, bi,   o);
                    if (ov > best || (ov == best && oi < bi)){ best = ov; bi = oi; }
                }
            }
            if (lane == 0) sm_ids[b] = (s > 0) ? bi : 0;
        }
        __syncthreads();

        // ---- phase A: 48 gate dots + h update + distributed score partials ----
        for (int d = w; d < 48; d += 16){
            float a[BB] = {0.f,0.f,0.f,0.f};
            int dd = (d < 24) ? d : d - 24;
            int jl = dd/3, g = dd%3;
            int row = g*HH + j0 + jl;
            if (d < 24){
                const float4* Wr = (const float4*)(sWih + dd*HH);
                const float4* em[BB];
                #pragma unroll
                for (int b = 0; b < BB; b++)
                    em[b] = (const float4*)(dec_emb + (size_t)sm_ids[b] * EE);
                #pragma unroll
                for (int i = 0; i < 8; i++){
                    int k4 = lane + 32*i;
                    float4 wv = Wr[k4];
                    #pragma unroll
                    for (int b = 0; b < BB; b++){
                        float4 xv = (k4 < 128) ? em[b][k4]
                                               : ((const float4*)d_av[cur][b])[k4 - 128];
                        a[b] += wv.x*xv.x + wv.y*xv.y + wv.z*xv.z + wv.w*xv.w;
                    }
                }
                #pragma unroll
                for (int b = 0; b < BB; b++){
                    float r = wred(a[b]);
                    if (lane == 0) sm_ge[d*BB + b] = r + dec_bih[row];
                }
            } else {
                const float4* Wr = (const float4*)(sWhh + dd*HH);
                #pragma unroll
                for (int i = 0; i < 8; i++){
                    int k4 = lane + 32*i;
                    float4 wv = Wr[k4];
                    #pragma unroll
                    for (int b = 0; b < BB; b++){
                        float4 hv = ((const float4*)d_h[cur][b])[k4];
                        a[b] += wv.x*hv.x + wv.y*hv.y + wv.z*hv.z + wv.w*hv.w;
                    }
                }
                #pragma unroll
                for (int b = 0; b < BB; b++){
                    float r = wred(a[b]);
                    if (lane == 0) sm_ge[d*BB + b] = r + dec_bhh[row];
                }
            }
        }
        __syncthreads();
        if (tid < 32){
            int jl = tid >> 2, b = tid & 3, j = j0 + jl;
            float ir  = sm_ge[(jl*3+0)*BB+b], iz = sm_ge[(jl*3+1)*BB+b], inn = sm_ge[(jl*3+2)*BB+b];
            float gr  = sm_ge[(24+jl*3+0)*BB+b], gz = sm_ge[(24+jl*3+1)*BB+b], gn = sm_ge[(24+jl*3+2)*BB+b];
            float r = sigm(ir + gr), z = sigm(iz + gz);
            float n = tanhf(inn + r*gn);
            float hp = d_h[cur][b][j];
            float hn = (1.f - z)*n + z*hp;
            d_h[nxt][b][j] = hn;
            sm_hloc[jl*4 + b] = hn;
        }
        __syncthreads();
        {   // one (b,t) score partial per thread over this block's 8 h dims
            int t = tid & 127, b = tid >> 7;
            const float4* eo = (const float4*)(&d_enc_out[b][t][j0]);
            float4 e0 = eo[0], e1 = eo[1];
            float p = e0.x*sm_hloc[0*4+b] + e0.y*sm_hloc[1*4+b]
                    + e0.z*sm_hloc[2*4+b] + e0.w*sm_hloc[3*4+b]
                    + e1.x*sm_hloc[4*4+b] + e1.y*sm_hloc[5*4+b]
                    + e1.z*sm_hloc[6*4+b] + e1.w*sm_hloc[7*4+b];
            long long pi = llrintf(p * SCALE);
            atomicAdd(&d_score_i[b*TT + t], (unsigned long long)pi);
        }
        gbar(bl, ++bgen);

        // ---- phase B: softmax (redundant) + attn_vec ----
        {
            if (w < 4){
                int b = w;
                float x[4];
                float m = -1e30f;
                #pragma unroll
                for (int i = 0; i < 4; i++){
                    int t = lane + 32*i;
                    long long v = (long long)d_score_i[b*TT + t];
                    float sc = (float)v * INV_SCALE;
                    if (inputs[b*TT + t] == 0) sc = -1e30f;
                    x[i] = sc; m = fmaxf(m, sc);
                }
                #pragma unroll
                for (int o = 16; o; o >>= 1) m = fmaxf(m, __shfl_xor_sync(0xffffffffu, m, o));
                float sum = 0.f;
                #pragma unroll
                for (int i = 0; i < 4; i++){ x[i] = expf(x[i] - m); sum += x[i]; }
                #pragma unroll
                for (int o = 16; o; o >>= 1) sum += __shfl_xor_sync(0xffffffffu, sum, o);
                float inv = 1.f / sum;
                #pragma unroll
                for (int i = 0; i < 4; i++) sm_w[b*TT + lane + 32*i] = x[i] * inv;
            }
            __syncthreads();
            {
                int b = w & 3, a = bl*4 + (w >> 2);
                float acc = 0.f;
                #pragma unroll
                for (int i = 0; i < 4; i++){
                    int t = lane + 32*i;
                    acc += sm_w[b*TT + t] * d_P[b][a][t];
                }
                const float4* Wr = (const float4*)(W_av + (size_t)a*2*HH + HH);
                const float4* hv = (const float4*)d_h[nxt][b];
                #pragma unroll
                for (int i = 0; i < 8; i++){
                    int k4 = lane + 32*i;
                    float4 wv = Wr[k4]; float4 h4 = hv[k4];
                    acc += wv.x*h4.x + wv.y*h4.y + wv.z*h4.z + wv.w*h4.w;
                }
                acc = wred(acc);
                if (lane == 0) d_av[nxt][b][a] = tanhf(acc + b_av[a]);
            }
            if (bl < BB && tid < TT)
                out[OUT_ATT + ((size_t)s*BB + bl)*TT + tid] = sm_w[bl*TT + tid];
        }
        gbar(bl, ++bgen);

        // ---- phase C: logits + argmax candidates + score-slot reset ----
        {
            for (int i = tid; i < BB*AA/4; i += NT)
                ((float4*)sm_av)[i] = ((const float4*)(&d_av[nxt][0][0]))[i];
            if (tid < 4) d_score_i[bl*4 + tid] = 0ull;
            __syncthreads();
            float bestv[BB] = {-3.4e38f,-3.4e38f,-3.4e38f,-3.4e38f};
            int   besti[BB] = {0,0,0,0};
            for (int r = w; r < 125; r += 16){
                int v = base_v + r;
                const float4* Wr = (const float4*)(W_cls + (size_t)v * AA);
                float a[BB] = {0.f,0.f,0.f,0.f};
                #pragma unroll
                for (int i = 0; i < 4; i++){
                    int k4 = lane + 32*i;
                    float4 wv = Wr[k4];
                    #pragma unroll
                    for (int b = 0; b < BB; b++){
                        float4 av4 = ((const float4*)(sm_av + b*AA))[k4];
                        a[b] += wv.x*av4.x + wv.y*av4.y + wv.z*av4.z + wv.w*av4.w;
                    }
                }
                #pragma unroll
                for (int b = 0; b < BB; b++){
                    float lg = wred(a[b]);
                    if (lane == 0){
                        lg += b_cls[v];
                        sm_lg[b*125 + r] = lg;
                        if (lg > bestv[b]){ bestv[b] = lg; besti[b] = v; }
                    }
                }
            }
            if (lane == 0){
                #pragma unroll
                for (int b = 0; b < BB; b++){ sm_bv[w*BB + b] = bestv[b]; sm_bi[w*BB + b] = besti[b]; }
            }
            __syncthreads();
            for (int i = tid; i < BB*125; i += NT){
                int b = i / 125, r = i % 125;
                out[((size_t)s*BB + b)*VV + base_v + r] = sm_lg[i];
            }
            if (tid < BB){
                int b = tid;
                float best = -3.4e38f; int bi = 0;
                for (int w2 = 0; w2 < 16; w2++){
                    float v = sm_bv[w2*BB + b]; int i2 = sm_bi[w2*BB + b];
                    if (v > best || (v == best && i2 < bi)){ best = v; bi = i2; }
                }
                d_cval[bl][b] = best; d_cidx[bl][b] = bi;
            }
        }
        gbar(bl, ++bgen);
    }
}

extern "C" void kernel_launch(void* const* d_in, const int* in_sizes, int n_in,
                              void* d_out, int out_size)
{
    (void)in_sizes; (void)n_in; (void)out_size;
    cudaFuncSetAttribute(seq2seq_kernel, cudaFuncAttributeMaxDynamicSharedMemorySize, DSMEM);
    seq2seq_kernel<<<NB, NT, DSMEM>>>(
        (const int*)  d_in[0],
        (const float*)d_in[1],  (const float*)d_in[2],  (const float*)d_in[3],
        (const float*)d_in[4],  (const float*)d_in[5],
        (const float*)d_in[6],  (const float*)d_in[7],  (const float*)d_in[8],
        (const float*)d_in[9],  (const float*)d_in[10],
        (const float*)d_in[11], (const float*)d_in[12],
        (const float*)d_in[13], (const float*)d_in[14],
        (float*)d_out);
}

// round 13
// speedup vs baseline: 1.3888x; 1.1625x over previous
#include <cuda_runtime.h>
#include <math.h>

#define BB 4
#define TT 128
#define HH 1024
#define EE 512
#define AA 512
#define VV 16000
#define SS 512
#define NB 128
#define NT 512
#define DSMEM (48*1024*4)
#define SCALE 1073741824.0f
#define INV_SCALE 9.313225746154785e-10f

// ---------------- persistent device state ----------------
__device__ __align__(16) float d_h[2][BB][HH];
__device__ __align__(16) float d_av[2][BB][AA];
__device__ __align__(16) float d_enc_out[BB][TT][HH];
__device__ __align__(16) float d_P[BB][AA][TT];
__device__ __align__(16) float d_gi[TT][BB][3*HH];
__device__ unsigned long long d_score_i[BB*TT];
__device__ unsigned long long d_best[2][BB];
__device__ unsigned d_cnt2;
__device__ unsigned d_flag[NB*64];   // one flag per block, 256B apart

__device__ __forceinline__ float wred(float v){
    #pragma unroll
    for (int o = 16; o; o >>= 1) v += __shfl_down_sync(0xffffffffu, v, o);
    return v;
}
__device__ __forceinline__ float sigm(float x){ return 1.0f / (1.0f + expf(-x)); }

// packed f32x2 fma: d = a*b + c elementwise on two fp32 lanes (Blackwell FFMA2)
__device__ __forceinline__ unsigned long long fma2(double a, double b, unsigned long long c){
    unsigned long long r;
    asm("fma.rn.f32x2 %0, %1, %2, %3;" : "=l"(r)
        : "l"(__double_as_longlong(a)), "l"(__double_as_longlong(b)), "l"(c));
    return r;
}
__device__ __forceinline__ float upk(unsigned long long a){
    return __uint_as_float((unsigned)a) + __uint_as_float((unsigned)(a >> 32));
}
// order-preserving (value, first-index) packing for atomicMax argmax
__device__ __forceinline__ unsigned long long packbest(float v, int idx){
    unsigned b = __float_as_uint(v);
    unsigned e = (b & 0x80000000u) ? ~b : (b | 0x80000000u);
    return ((unsigned long long)e << 32) | (unsigned long long)(0xFFFFFFFFu - (unsigned)idx);
}

// grid barrier: single arrival counter + per-block release flags (warp fan-out)
__device__ __forceinline__ void gbar(int bl, unsigned gen){
    __syncthreads();
    if (threadIdx.x < 32){
        int lane = threadIdx.x;
        unsigned old = 0u;
        if (lane == 0)
            asm volatile("atom.acq_rel.gpu.add.u32 %0, [%1], 1;" : "=r"(old) : "l"(&d_cnt2) : "memory");
        old = __shfl_sync(0xffffffffu, old, 0);
        if (old == (unsigned)(NB - 1)){
            if (lane == 0) d_cnt2 = 0u;
            __syncwarp();
            asm volatile("fence.acq_rel.gpu;" ::: "memory");
            #pragma unroll
            for (int i = 0; i < 4; i++)
                asm volatile("st.relaxed.gpu.u32 [%0], %1;"
                             :: "l"(&d_flag[(lane*4 + i)*64]), "r"(gen) : "memory");
        }
        if (lane == 0){
            unsigned f;
            do {
                asm volatile("ld.acquire.gpu.u32 %0, [%1];" : "=r"(f) : "l"(&d_flag[bl*64]) : "memory");
            } while (f != gen);
        }
    }
    __syncthreads();
}

__global__ __launch_bounds__(NT, 1) void seq2seq_kernel(
    const int*   __restrict__ inputs,
    const float* __restrict__ enc_emb, const float* __restrict__ enc_Wih,
    const float* __restrict__ enc_Whh, const float* __restrict__ enc_bih,
    const float* __restrict__ enc_bhh,
    const float* __restrict__ dec_emb, const float* __restrict__ dec_Wih,
    const float* __restrict__ dec_Whh, const float* __restrict__ dec_bih,
    const float* __restrict__ dec_bhh,
    const float* __restrict__ W_av,  const float* __restrict__ b_av,
    const float* __restrict__ W_cls, const float* __restrict__ b_cls,
    float* __restrict__ out)
{
    extern __shared__ __align__(16) float dyn[];
    float* sWih = dyn;              // 24x1024 decoder ih rows
    float* sWhh = dyn + 24*HH;      // 24x1024 (enc rows during encoder, then dec hh rows)

    __shared__ float sm_w[BB*TT];
    __shared__ float sm_lg[BB*125];
    __shared__ float sm_ge[48*BB];
    __shared__ float sm_hloc[8*BB];
    __shared__ float sm_bv[16*BB];
    __shared__ int   sm_bi[16*BB];
    __shared__ int   sm_ids[BB];

    const int tid  = threadIdx.x;
    const int bl   = blockIdx.x;
    const int w    = tid >> 5;
    const int lane = tid & 31;
    const int j0   = bl * 8;
    unsigned bgen = 0;

    if (tid == 0) d_flag[bl*64] = 0u;
    if (bl == 0 && tid < 8) ((unsigned long long*)d_best)[tid] = 0ull;

    // ---- zero recurrent state (replay determinism) ----
    for (int i = bl*NT + tid; i < 2*BB*HH + 2*BB*AA; i += NB*NT){
        if (i < 2*BB*HH) (&d_h[0][0][0])[i] = 0.f;
        else             (&d_av[0][0][0])[i - 2*BB*HH] = 0.f;
    }

    // ---- load this block's 24 enc_Whh rows to SMEM ----
    for (int i = tid; i < 24*HH; i += NT){
        int d = i >> 10, k = i & 1023;
        int jl = d/3, g = d%3;
        sWhh[i] = enc_Whh[(size_t)(g*HH + j0 + jl)*HH + k];
    }

    // ---- setup A: encoder input-gate preactivations ----
    {
        int r0 = bl * 24;
        if (w < 12){
            int row0 = r0 + 2*w, row1 = row0 + 1;
            float w0[16], w1[16];
            #pragma unroll
            for (int i = 0; i < 16; i++){
                w0[i] = enc_Wih[row0*EE + lane + 32*i];
                w1[i] = enc_Wih[row1*EE + lane + 32*i];
            }
            float b0 = enc_bih[row0], b1 = enc_bih[row1];
            for (int tb = 0; tb < TT*BB; tb++){
                int t = tb >> 2, b = tb & 3;
                int tok = inputs[b*TT + t];
                const float* em = enc_emb + (size_t)tok * EE;
                float a0 = 0.f, a1 = 0.f;
                #pragma unroll
                for (int i = 0; i < 16; i++){
                    float e = em[lane + 32*i];
                    a0 += w0[i]*e; a1 += w1[i]*e;
                }
                a0 = wred(a0); a1 = wred(a1);
                if (lane == 0){
                    d_gi[t][b][row0] = a0 + b0;
                    d_gi[t][b][row1] = a1 + b1;
                }
            }
        }
    }
    gbar(bl, ++bgen);

    // ---- encoder scan (SMEM weights, f32x2) ----
    for (int t = 0; t < TT; t++){
        int cur = t & 1, nxt = cur ^ 1;
        for (int d = w; d < 24; d += 16){
            int jl = d/3, g = d%3;
            int row = g*HH + j0 + jl;
            const double2* Wr = (const double2*)(sWhh + d*HH);
            unsigned long long a2[BB] = {0ull,0ull,0ull,0ull};
            #pragma unroll
            for (int i = 0; i < 8; i++){
                int k4 = lane + 32*i;
                double2 wv = Wr[k4];
                #pragma unroll
                for (int b = 0; b < BB; b++){
                    double2 hv = ((const double2*)d_h[cur][b])[k4];
                    a2[b] = fma2(wv.x, hv.x, a2[b]);
                    a2[b] = fma2(wv.y, hv.y, a2[b]);
                }
            }
            #pragma unroll
            for (int b = 0; b < BB; b++){
                float r = wred(upk(a2[b]));
                if (lane == 0) sm_ge[d*BB + b] = r + enc_bhh[row];
            }
        }
        __syncthreads();
        if (tid < 32){
            int jl = tid >> 2, b = tid & 3, j = j0 + jl;
            float gr = sm_ge[(jl*3+0)*BB+b], gz = sm_ge[(jl*3+1)*BB+b], gn = sm_ge[(jl*3+2)*BB+b];
            float ir = d_gi[t][b][j], iz = d_gi[t][b][j+HH], inn = d_gi[t][b][j+2*HH];
            float r = sigm(ir + gr), z = sigm(iz + gz);
            float n = tanhf(inn + r*gn);
            float hp = d_h[cur][b][j];
            float hn = (1.f - z)*n + z*hp;
            d_h[nxt][b][j]     = hn;
            d_enc_out[b][t][j] = hn;
        }
        gbar(bl, ++bgen);
    }

    // ---- setup P: P[b][a][t] = W_av_left[a] . enc_out[b][t] ----
    {
        int a = bl*4 + (w & 3);
        int q = w >> 2;
        float wa[32];
        #pragma unroll
        for (int i = 0; i < 32; i++) wa[i] = W_av[(size_t)a*2*HH + lane + 32*i];
        for (int tb = q*128; tb < q*128 + 128; tb++){
            int t = tb >> 2, b = tb & 3;
            const float* eo = d_enc_out[b][t];
            float acc = 0.f;
            #pragma unroll
            for (int i = 0; i < 32; i++) acc += wa[i] * eo[lane + 32*i];
            acc = wred(acc);
            if (lane == 0) d_P[b][a][t] = acc;
        }
    }
    if (tid < 4) d_score_i[bl*4 + tid] = 0ull;
    gbar(bl, ++bgen);

    // ---- load decoder weight rows to SMEM ----
    for (int i = tid; i < 24*HH; i += NT){
        int d = i >> 10, k = i & 1023;
        int jl = d/3, g = d%3;
        size_t row = (size_t)(g*HH + j0 + jl);
        sWih[i] = dec_Wih[row*(size_t)(EE+AA) + k];
        sWhh[i] = dec_Whh[row*(size_t)HH + k];
    }

    // ---- decoder: 512 greedy steps, 3 grid barriers each ----
    const int base_v = bl * 125;
    const size_t OUT_ATT = (size_t)SS * BB * VV;

    for (int s = 0; s < SS; s++){
        int cur = s & 1, nxt = cur ^ 1;

        // ids from previous step's packed argmax
        if (tid < BB){
            int idv = 0;
            if (s > 0){
                unsigned long long p = d_best[nxt][tid];
                idv = (int)(0xFFFFFFFFu - (unsigned)(p & 0xFFFFFFFFull));
            }
            sm_ids[tid] = idv;
        }
        __syncthreads();

        // ---- phase A: row-grouped gate dots (f32x2) + h update + score partials ----
        {
            unsigned long long a2[3][BB];
            #pragma unroll
            for (int r = 0; r < 3; r++)
                #pragma unroll
                for (int b = 0; b < BB; b++) a2[r][b] = 0ull;

            if (w < 8){
                // 3 ih rows: jl=w, g=0..2 ; x = [emb(512); av(512)]
                const double2* W0 = (const double2*)(sWih + (3*w+0)*HH);
                const double2* W1 = (const double2*)(sWih + (3*w+1)*HH);
                const double2* W2 = (const double2*)(sWih + (3*w+2)*HH);
                const double2* em[BB];
                #pragma unroll
                for (int b = 0; b < BB; b++)
                    em[b] = (const double2*)(dec_emb + (size_t)sm_ids[b] * EE);
                #pragma unroll
                for (int i = 0; i < 8; i++){
                    int k4 = lane + 32*i;
                    double2 w0 = W0[k4], w1 = W1[k4], w2 = W2[k4];
                    #pragma unroll
                    for (int b = 0; b < BB; b++){
                        double2 xv = (i < 4) ? em[b][k4]
                                             : ((const double2*)d_av[cur][b])[k4 - 128];
                        a2[0][b] = fma2(w0.x, xv.x, a2[0][b]);
                        a2[0][b] = fma2(w0.y, xv.y, a2[0][b]);
                        a2[1][b] = fma2(w1.x, xv.x, a2[1][b]);
                        a2[1][b] = fma2(w1.y, xv.y, a2[1][b]);
                        a2[2][b] = fma2(w2.x, xv.x, a2[2][b]);
                        a2[2][b] = fma2(w2.y, xv.y, a2[2][b]);
                    }
                }
                #pragma unroll
                for (int r = 0; r < 3; r++){
                    int row = r*HH + j0 + w;
                    #pragma unroll
                    for (int b = 0; b < BB; b++){
                        float v = wred(upk(a2[r][b]));
                        if (lane == 0) sm_ge[(3*w+r)*BB + b] = v + dec_bih[row];
                    }
                }
            } else {
                // 3 hh rows: jl=w-8, g=0..2 ; act = h
                int u = w - 8;
                const double2* W0 = (const double2*)(sWhh + (3*u+0)*HH);
                const double2* W1 = (const double2*)(sWhh + (3*u+1)*HH);
                const double2* W2 = (const double2*)(sWhh + (3*u+2)*HH);
                #pragma unroll
                for (int i = 0; i < 8; i++){
                    int k4 = lane + 32*i;
                    double2 w0 = W0[k4], w1 = W1[k4], w2 = W2[k4];
                    #pragma unroll
                    for (int b = 0; b < BB; b++){
                        double2 hv = ((const double2*)d_h[cur][b])[k4];
                        a2[0][b] = fma2(w0.x, hv.x, a2[0][b]);
                        a2[0][b] = fma2(w0.y, hv.y, a2[0][b]);
                        a2[1][b] = fma2(w1.x, hv.x, a2[1][b]);
                        a2[1][b] = fma2(w1.y, hv.y, a2[1][b]);
                        a2[2][b] = fma2(w2.x, hv.x, a2[2][b]);
                        a2[2][b] = fma2(w2.y, hv.y, a2[2][b]);
                    }
                }
                #pragma unroll
                for (int r = 0; r < 3; r++){
                    int row = r*HH + j0 + u;
                    #pragma unroll
                    for (int b = 0; b < BB; b++){
                        float v = wred(upk(a2[r][b]));
                        if (lane == 0) sm_ge[(24 + 3*u + r)*BB + b] = v + dec_bhh[row];
                    }
                }
            }
        }
        __syncthreads();
        if (tid < 32){
            int jl = tid >> 2, b = tid & 3, j = j0 + jl;
            float ir  = sm_ge[(jl*3+0)*BB+b], iz = sm_ge[(jl*3+1)*BB+b], inn = sm_ge[(jl*3+2)*BB+b];
            float gr  = sm_ge[(24+jl*3+0)*BB+b], gz = sm_ge[(24+jl*3+1)*BB+b], gn = sm_ge[(24+jl*3+2)*BB+b];
            float r = sigm(ir + gr), z = sigm(iz + gz);
            float n = tanhf(inn + r*gn);
            float hp = d_h[cur][b][j];
            float hn = (1.f - z)*n + z*hp;
            d_h[nxt][b][j] = hn;
            sm_hloc[jl*4 + b] = hn;
        }
        __syncthreads();
        {   // one (b,t) score partial per thread over this block's 8 h dims
            int t = tid & 127, b = tid >> 7;
            const float4* eo = (const float4*)(&d_enc_out[b][t][j0]);
            float4 e0 = eo[0], e1 = eo[1];
            float p = e0.x*sm_hloc[0*4+b] + e0.y*sm_hloc[1*4+b]
                    + e0.z*sm_hloc[2*4+b] + e0.w*sm_hloc[3*4+b]
                    + e1.x*sm_hloc[4*4+b] + e1.y*sm_hloc[5*4+b]
                    + e1.z*sm_hloc[6*4+b] + e1.w*sm_hloc[7*4+b];
            long long pi = llrintf(p * SCALE);
            atomicAdd(&d_score_i[b*TT + t], (unsigned long long)pi);
        }
        gbar(bl, ++bgen);

        // ---- phase B: softmax (redundant) + attn_vec ----
        {
            if (bl == 0 && tid >= 480 && tid < 484)
                d_best[nxt][tid - 480] = 0ull;   // reset slot for step s+1's phase C
            if (w < 4){
                int b = w;
                float x[4];
                float m = -1e30f;
                #pragma unroll
                for (int i = 0; i < 4; i++){
                    int t = lane + 32*i;
                    long long v = (long long)d_score_i[b*TT + t];
                    float sc = (float)v * INV_SCALE;
                    if (inputs[b*TT + t] == 0) sc = -1e30f;
                    x[i] = sc; m = fmaxf(m, sc);
                }
                #pragma unroll
                for (int o = 16; o; o >>= 1) m = fmaxf(m, __shfl_xor_sync(0xffffffffu, m, o));
                float sum = 0.f;
                #pragma unroll
                for (int i = 0; i < 4; i++){ x[i] = expf(x[i] - m); sum += x[i]; }
                #pragma unroll
                for (int o = 16; o; o >>= 1) sum += __shfl_xor_sync(0xffffffffu, sum, o);
                float inv = 1.f / sum;
                #pragma unroll
                for (int i = 0; i < 4; i++) sm_w[b*TT + lane + 32*i] = x[i] * inv;
            }
            __syncthreads();
            {
                int b = w & 3, a = bl*4 + (w >> 2);
                float acc = 0.f;
                #pragma unroll
                for (int i = 0; i < 4; i++){
                    int t = lane + 32*i;
                    acc += sm_w[b*TT + t] * d_P[b][a][t];
                }
                // W_avR[a] . h  over the FULL 1024-wide h (8 x 32 x 4 floats)
                const double2* Wr = (const double2*)(W_av + (size_t)a*2*HH + HH);
                const double2* hv = (const double2*)d_h[nxt][b];
                unsigned long long a2 = 0ull;
                #pragma unroll
                for (int i = 0; i < 8; i++){
                    int k4 = lane + 32*i;
                    double2 wv = Wr[k4]; double2 h2 = hv[k4];
                    a2 = fma2(wv.x, h2.x, a2);
                    a2 = fma2(wv.y, h2.y, a2);
                }
                acc += upk(a2);
                acc = wred(acc);
                if (lane == 0) d_av[nxt][b][a] = tanhf(acc + b_av[a]);
            }
            if (bl < BB && tid < TT)
                out[OUT_ATT + ((size_t)s*BB + bl)*TT + tid] = sm_w[bl*TT + tid];
        }
        gbar(bl, ++bgen);

        // ---- phase C: logits (av register-stationary, f32x2) + packed argmax ----
        {
            double2 rav[BB][4];
            #pragma unroll
            for (int b = 0; b < BB; b++)
                #pragma unroll
                for (int i = 0; i < 4; i++)
                    rav[b][i] = ((const double2*)d_av[nxt][b])[lane + 32*i];
            if (tid < 4) d_score_i[bl*4 + tid] = 0ull;

            float bestv[BB] = {-3.4e38f,-3.4e38f,-3.4e38f,-3.4e38f};
            int   besti[BB] = {0,0,0,0};
            for (int r = w; r < 125; r += 16){
                int v = base_v + r;
                const double2* Wr = (const double2*)(W_cls + (size_t)v * AA);
                unsigned long long a2[BB] = {0ull,0ull,0ull,0ull};
                #pragma unroll
                for (int i = 0; i < 4; i++){
                    double2 wv = Wr[lane + 32*i];
                    #pragma unroll
                    for (int b = 0; b < BB; b++){
                        a2[b] = fma2(wv.x, rav[b][i].x, a2[b]);
                        a2[b] = fma2(wv.y, rav[b][i].y, a2[b]);
                    }
                }
                #pragma unroll
                for (int b = 0; b < BB; b++){
                    float lg = wred(upk(a2[b]));
                    if (lane == 0){
                        lg += b_cls[v];
                        sm_lg[b*125 + r] = lg;
                        if (lg > bestv[b]){ bestv[b] = lg; besti[b] = v; }
                    }
                }
            }
            if (lane == 0){
                #pragma unroll
                for (int b = 0; b < BB; b++){ sm_bv[w*BB + b] = bestv[b]; sm_bi[w*BB + b] = besti[b]; }
            }
            __syncthreads();
            for (int i = tid; i < BB*125; i += NT){
                int b = i / 125, r = i % 125;
                out[((size_t)s*BB + b)*VV + base_v + r] = sm_lg[i];
            }
            if (tid < BB){
                int b = tid;
                float best = -3.4e38f; int bi = 0;
                for (int w2 = 0; w2 < 16; w2++){
                    float v = sm_bv[w2*BB + b]; int i2 = sm_bi[w2*BB + b];
                    if (v > best || (v == best && i2 < bi)){ best = v; bi = i2; }
                }
                atomicMax(&d_best[cur][b], packbest(best, bi));
            }
        }
        gbar(bl, ++bgen);
    }
}

extern "C" void kernel_launch(void* const* d_in, const int* in_sizes, int n_in,
                              void* d_out, int out_size)
{
    (void)in_sizes; (void)n_in; (void)out_size;
    cudaFuncSetAttribute(seq2seq_kernel, cudaFuncAttributeMaxDynamicSharedMemorySize, DSMEM);
    seq2seq_kernel<<<NB, NT, DSMEM>>>(
        (const int*)  d_in[0],
        (const float*)d_in[1],  (const float*)d_in[2],  (const float*)d_in[3],
        (const float*)d_in[4],  (const float*)d_in[5],
        (const float*)d_in[6],  (const float*)d_in[7],  (const float*)d_in[8],
        (const float*)d_in[9],  (const float*)d_in[10],
        (const float*)d_in[11], (const float*)d_in[12],
        (const float*)d_in[13], (const float*)d_in[14],
        (float*)d_out);
}

// round 15
// speedup vs baseline: 1.4193x; 1.0220x over previous
#include <cuda_runtime.h>
#include <math.h>

#define BB 4
#define TT 128
#define HH 1024
#define EE 512
#define AA 512
#define VV 16000
#define SS 512
#define NB 128
#define NT 512
#define DSMEM ((24*1024*2 + 4096 + 2048)*4)
#define SCALE 1073741824.0f
#define INV_SCALE 9.313225746154785e-10f

// ---------------- persistent device state ----------------
__device__ __align__(16) float d_h[2][BB][HH];        // [0] is the decoder h buffer
__device__ __align__(16) float d_av1[BB][AA];
__device__ __align__(16) float d_enc_out[BB][TT][HH];
__device__ __align__(16) float d_P[BB][AA][TT];
__device__ __align__(16) float d_gi[TT][BB][3*HH];
__device__ unsigned long long d_score_i[BB*TT];
__device__ unsigned long long d_best[2][BB];
__device__ unsigned d_cnt2;
__device__ unsigned d_flag[NB*64];   // one flag per block, 256B apart

__device__ __forceinline__ float wred(float v){
    #pragma unroll
    for (int o = 16; o; o >>= 1) v += __shfl_down_sync(0xffffffffu, v, o);
    return v;
}
__device__ __forceinline__ float sigm(float x){ return 1.0f / (1.0f + expf(-x)); }

// packed f32x2 fma (Blackwell FFMA2)
__device__ __forceinline__ unsigned long long fma2(double a, double b, unsigned long long c){
    unsigned long long r;
    asm("fma.rn.f32x2 %0, %1, %2, %3;" : "=l"(r)
        : "l"(__double_as_longlong(a)), "l"(__double_as_longlong(b)), "l"(c));
    return r;
}
__device__ __forceinline__ float upk(unsigned long long a){
    return __uint_as_float((unsigned)a) + __uint_as_float((unsigned)(a >> 32));
}
// order-preserving (value, first-index) packing for atomicMax argmax
__device__ __forceinline__ unsigned long long packbest(float v, int idx){
    unsigned b = __float_as_uint(v);
    unsigned e = (b & 0x80000000u) ? ~b : (b | 0x80000000u);
    return ((unsigned long long)e << 32) | (unsigned long long)(0xFFFFFFFFu - (unsigned)idx);
}

// grid barrier: single arrival counter + per-block release flags (warp fan-out)
__device__ __forceinline__ void gbar(int bl, unsigned gen){
    __syncthreads();
    if (threadIdx.x < 32){
        int lane = threadIdx.x;
        unsigned old = 0u;
        if (lane == 0)
            asm volatile("atom.acq_rel.gpu.add.u32 %0, [%1], 1;" : "=r"(old) : "l"(&d_cnt2) : "memory");
        old = __shfl_sync(0xffffffffu, old, 0);
        if (old == (unsigned)(NB - 1)){
            if (lane == 0) d_cnt2 = 0u;
            __syncwarp();
            asm volatile("fence.acq_rel.gpu;" ::: "memory");
            #pragma unroll
            for (int i = 0; i < 4; i++)
                asm volatile("st.relaxed.gpu.u32 [%0], %1;"
                             :: "l"(&d_flag[(lane*4 + i)*64]), "r"(gen) : "memory");
        }
        if (lane == 0){
            unsigned f;
            do {
                asm volatile("ld.acquire.gpu.u32 %0, [%1];" : "=r"(f) : "l"(&d_flag[bl*64]) : "memory");
            } while (f != gen);
        }
    }
    __syncthreads();
}

__global__ __launch_bounds__(NT, 1) void seq2seq_kernel(
    const int*   __restrict__ inputs,
    const float* __restrict__ enc_emb, const float* __restrict__ enc_Wih,
    const float* __restrict__ enc_Whh, const float* __restrict__ enc_bih,
    const float* __restrict__ enc_bhh,
    const float* __restrict__ dec_emb, const float* __restrict__ dec_Wih,
    const float* __restrict__ dec_Whh, const float* __restrict__ dec_bih,
    const float* __restrict__ dec_bhh,
    const float* __restrict__ W_av,  const float* __restrict__ b_av,
    const float* __restrict__ W_cls, const float* __restrict__ b_cls,
    float* __restrict__ out)
{
    extern __shared__ __align__(16) float dyn[];
    float* sWih  = dyn;               // 24x1024 decoder ih rows
    float* sWhh  = dyn + 24*HH;       // 24x1024 (enc rows during encoder, then dec hh rows)
    float* sm_hst = dyn + 48*HH;      // BB*HH staged h (16 KB)
    float* sm_avv = dyn + 48*HH + BB*HH; // BB*AA staged av (8 KB)

    __shared__ float sm_lg[BB*125];
    __shared__ float sm_ge[48*BB];
    __shared__ float sm_hloc[8*BB];
    __shared__ float sm_bv[16*BB];
    __shared__ int   sm_bi[16*BB];
    __shared__ int   sm_maski[BB*TT];
    __shared__ float sm_bcls[125];
    __shared__ float sm_bih[24];
    __shared__ float sm_bhh[24];
    __shared__ float sm_bav[4];

    const int tid  = threadIdx.x;
    const int bl   = blockIdx.x;
    const int w    = tid >> 5;
    const int lane = tid & 31;
    const int j0   = bl * 8;
    const int base_v = bl * 125;
    unsigned bgen = 0;

    if (tid == 0) d_flag[bl*64] = 0u;
    if (bl == 0 && tid < 8) ((unsigned long long*)d_best)[tid] = 0ull;

    // ---- zero recurrent state (replay determinism) ----
    for (int i = bl*NT + tid; i < 2*BB*HH + BB*AA; i += NB*NT){
        if (i < 2*BB*HH) (&d_h[0][0][0])[i] = 0.f;
        else             (&d_av1[0][0])[i - 2*BB*HH] = 0.f;
    }

    // ---- load this block's 24 enc_Whh rows to SMEM ----
    for (int i = tid; i < 24*HH; i += NT){
        int d = i >> 10, k = i & 1023;
        int jl = d/3, g = d%3;
        sWhh[i] = enc_Whh[(size_t)(g*HH + j0 + jl)*HH + k];
    }

    // ---- setup A: encoder input-gate preactivations ----
    {
        int r0 = bl * 24;
        if (w < 12){
            int row0 = r0 + 2*w, row1 = row0 + 1;
            float w0[16], w1[16];
            #pragma unroll
            for (int i = 0; i < 16; i++){
                w0[i] = enc_Wih[row0*EE + lane + 32*i];
                w1[i] = enc_Wih[row1*EE + lane + 32*i];
            }
            float b0 = enc_bih[row0], b1 = enc_bih[row1];
            for (int tb = 0; tb < TT*BB; tb++){
                int t = tb >> 2, b = tb & 3;
                int tok = inputs[b*TT + t];
                const float* em = enc_emb + (size_t)tok * EE;
                float a0 = 0.f, a1 = 0.f;
                #pragma unroll
                for (int i = 0; i < 16; i++){
                    float e = em[lane + 32*i];
                    a0 += w0[i]*e; a1 += w1[i]*e;
                }
                a0 = wred(a0); a1 = wred(a1);
                if (lane == 0){
                    d_gi[t][b][row0] = a0 + b0;
                    d_gi[t][b][row1] = a1 + b1;
                }
            }
        }
    }
    gbar(bl, ++bgen);

    // ---- encoder scan (SMEM weights, f32x2) ----
    for (int t = 0; t < TT; t++){
        int cur = t & 1, nxt = cur ^ 1;
        for (int d = w; d < 24; d += 16){
            int jl = d/3, g = d%3;
            int row = g*HH + j0 + jl;
            const double2* Wr = (const double2*)(sWhh + d*HH);
            unsigned long long a2[BB] = {0ull,0ull,0ull,0ull};
            #pragma unroll
            for (int i = 0; i < 8; i++){
                int k4 = lane + 32*i;
                double2 wv = Wr[k4];
                #pragma unroll
                for (int b = 0; b < BB; b++){
                    double2 hv = ((const double2*)d_h[cur][b])[k4];
                    a2[b] = fma2(wv.x, hv.x, a2[b]);
                    a2[b] = fma2(wv.y, hv.y, a2[b]);
                }
            }
            #pragma unroll
            for (int b = 0; b < BB; b++){
                float r = wred(upk(a2[b]));
                if (lane == 0) sm_ge[d*BB + b] = r + enc_bhh[row];
            }
        }
        __syncthreads();
        if (tid < 32){
            int jl = tid >> 2, b = tid & 3, j = j0 + jl;
            float gr = sm_ge[(jl*3+0)*BB+b], gz = sm_ge[(jl*3+1)*BB+b], gn = sm_ge[(jl*3+2)*BB+b];
            float ir = d_gi[t][b][j], iz = d_gi[t][b][j+HH], inn = d_gi[t][b][j+2*HH];
            float r = sigm(ir + gr), z = sigm(iz + gz);
            float n = tanhf(inn + r*gn);
            float hp = d_h[cur][b][j];
            float hn = (1.f - z)*n + z*hp;
            d_h[nxt][b][j]     = hn;
            d_enc_out[b][t][j] = hn;
        }
        gbar(bl, ++bgen);
    }

    // ---- setup P: P[b][a][t] = W_av_left[a] . enc_out[b][t] ----
    {
        int a = bl*4 + (w & 3);
        int q = w >> 2;
        float wa[32];
        #pragma unroll
        for (int i = 0; i < 32; i++) wa[i] = W_av[(size_t)a*2*HH + lane + 32*i];
        for (int tb = q*128; tb < q*128 + 128; tb++){
            int t = tb >> 2, b = tb & 3;
            const float* eo = d_enc_out[b][t];
            float acc = 0.f;
            #pragma unroll
            for (int i = 0; i < 32; i++) acc += wa[i] * eo[lane + 32*i];
            acc = wred(acc);
            if (lane == 0) d_P[b][a][t] = acc;
        }
    }
    if (tid < 4) d_score_i[bl*4 + tid] = 0ull;
    gbar(bl, ++bgen);

    // ---- load decoder weight rows to SMEM + stage caches ----
    for (int i = tid; i < 24*HH; i += NT){
        int d = i >> 10, k = i & 1023;
        int jl = d/3, g = d%3;
        size_t row = (size_t)(g*HH + j0 + jl);
        sWih[i] = dec_Wih[row*(size_t)(EE+AA) + k];
        sWhh[i] = dec_Whh[row*(size_t)HH + k];
    }
    if (tid < BB*TT) sm_maski[tid] = (inputs[tid] == 0) ? 1 : 0;
    if (tid < 125)  sm_bcls[tid] = b_cls[base_v + tid];
    if (tid < 24){ int jl = tid/3, g = tid%3; sm_bih[tid] = dec_bih[g*HH + j0 + jl];
                   sm_bhh[tid] = dec_bhh[g*HH + j0 + jl]; }
    if (tid < 4)   sm_bav[tid] = b_av[bl*4 + tid];
    for (int i = tid; i < BB*HH/4; i += NT) ((float4*)sm_hst)[i] = ((const float4*)(&d_h[0][0][0]))[i];
    for (int i = tid; i < BB*AA/4; i += NT) ((float4*)sm_avv)[i] = ((const float4*)(&d_av1[0][0]))[i];
    __syncthreads();

    // ---- decoder: 512 greedy steps, 3 grid barriers each ----
    const size_t OUT_ATT = (size_t)SS * BB * VV;

    for (int s = 0; s < SS; s++){
        int cur = s & 1, nxt = cur ^ 1;

        // per-warp ids decode from previous step's packed argmax
        int myid = 0;
        if (s > 0){
            unsigned long long p = d_best[nxt][lane & 3];
            myid = (int)(0xFFFFFFFFu - (unsigned)(p & 0xFFFFFFFFull));
        }

        // ---- phase A: row-grouped gate dots (SMEM acts, f32x2) + h update + score partials ----
        {
            unsigned long long a2[3][BB];
            #pragma unroll
            for (int r = 0; r < 3; r++)
                #pragma unroll
                for (int b = 0; b < BB; b++) a2[r][b] = 0ull;

            if (w < 8){
                const double2* W0 = (const double2*)(sWih + (3*w+0)*HH);
                const double2* W1 = (const double2*)(sWih + (3*w+1)*HH);
                const double2* W2 = (const double2*)(sWih + (3*w+2)*HH);
                const double2* em[BB];
                #pragma unroll
                for (int b = 0; b < BB; b++)
                    em[b] = (const double2*)(dec_emb + (size_t)__shfl_sync(0xffffffffu, myid, b) * EE);
                #pragma unroll
                for (int i = 0; i < 8; i++){
                    int k4 = lane + 32*i;
                    double2 w0 = W0[k4], w1 = W1[k4], w2 = W2[k4];
                    #pragma unroll
                    for (int b = 0; b < BB; b++){
                        double2 xv = (i < 4) ? em[b][k4]
                                             : ((const double2*)(sm_avv + b*AA))[k4 - 128];
                        a2[0][b] = fma2(w0.x, xv.x, a2[0][b]);
                        a2[0][b] = fma2(w0.y, xv.y, a2[0][b]);
                        a2[1][b] = fma2(w1.x, xv.x, a2[1][b]);
                        a2[1][b] = fma2(w1.y, xv.y, a2[1][b]);
                        a2[2][b] = fma2(w2.x, xv.x, a2[2][b]);
                        a2[2][b] = fma2(w2.y, xv.y, a2[2][b]);
                    }
                }
                #pragma unroll
                for (int r = 0; r < 3; r++)
                    #pragma unroll
                    for (int b = 0; b < BB; b++){
                        float v = wred(upk(a2[r][b]));
                        if (lane == 0) sm_ge[(3*w+r)*BB + b] = v + sm_bih[3*w+r];
                    }
            } else {
                int u = w - 8;
                const double2* W0 = (const double2*)(sWhh + (3*u+0)*HH);
                const double2* W1 = (const double2*)(sWhh + (3*u+1)*HH);
                const double2* W2 = (const double2*)(sWhh + (3*u+2)*HH);
                #pragma unroll
                for (int i = 0; i < 8; i++){
                    int k4 = lane + 32*i;
                    double2 w0 = W0[k4], w1 = W1[k4], w2 = W2[k4];
                    #pragma unroll
                    for (int b = 0; b < BB; b++){
                        double2 hv = ((const double2*)(sm_hst + b*HH))[k4];
                        a2[0][b] = fma2(w0.x, hv.x, a2[0][b]);
                        a2[0][b] = fma2(w0.y, hv.y, a2[0][b]);
                        a2[1][b] = fma2(w1.x, hv.x, a2[1][b]);
                        a2[1][b] = fma2(w1.y, hv.y, a2[1][b]);
                        a2[2][b] = fma2(w2.x, hv.x, a2[2][b]);
                        a2[2][b] = fma2(w2.y, hv.y, a2[2][b]);
                    }
                }
                #pragma unroll
                for (int r = 0; r < 3; r++)
                    #pragma unroll
                    for (int b = 0; b < BB; b++){
                        float v = wred(upk(a2[r][b]));
                        if (lane == 0) sm_ge[(24 + 3*u + r)*BB + b] = v + sm_bhh[3*u+r];
                    }
            }
        }
        __syncthreads();
        if (tid < 32){
            int jl = tid >> 2, b = tid & 3, j = j0 + jl;
            float ir  = sm_ge[(jl*3+0)*BB+b], iz = sm_ge[(jl*3+1)*BB+b], inn = sm_ge[(jl*3+2)*BB+b];
            float gr  = sm_ge[(24+jl*3+0)*BB+b], gz = sm_ge[(24+jl*3+1)*BB+b], gn = sm_ge[(24+jl*3+2)*BB+b];
            float r = sigm(ir + gr), z = sigm(iz + gz);
            float n = tanhf(inn + r*gn);
            float hp = sm_hst[b*HH + j];
            float hn = (1.f - z)*n + z*hp;
            d_h[0][b][j] = hn;
            sm_hloc[jl*4 + b] = hn;
        }
        __syncthreads();
        {   // one (b,t) score partial per thread over this block's 8 h dims
            int t = tid & 127, b = tid >> 7;
            const float4* eo = (const float4*)(&d_enc_out[b][t][j0]);
            float4 e0 = eo[0], e1 = eo[1];
            float p = e0.x*sm_hloc[0*4+b] + e0.y*sm_hloc[1*4+b]
                    + e0.z*sm_hloc[2*4+b] + e0.w*sm_hloc[3*4+b]
                    + e1.x*sm_hloc[4*4+b] + e1.y*sm_hloc[5*4+b]
                    + e1.z*sm_hloc[6*4+b] + e1.w*sm_hloc[7*4+b];
            long long pi = llrintf(p * SCALE);
            atomicAdd(&d_score_i[b*TT + t], (unsigned long long)pi);
        }
        gbar(bl, ++bgen);

        // ---- phase B: warp-local softmax + attn_vec (no block syncs) ----
        {
            if (bl == 0 && tid >= 480 && tid < 484)
                d_best[nxt][tid - 480] = 0ull;   // reset slot for step s+1's phase C
            int b = w & 3, aq = w >> 2, a = bl*4 + aq;
            float x[4]; float m = -1e30f;
            #pragma unroll
            for (int i = 0; i < 4; i++){
                int t = lane + 32*i;
                long long v = (long long)d_score_i[b*TT + t];
                float sc = (float)v * INV_SCALE;
                if (sm_maski[b*TT + t]) sc = -1e30f;
                x[i] = sc; m = fmaxf(m, sc);
            }
            #pragma unroll
            for (int o = 16; o; o >>= 1) m = fmaxf(m, __shfl_xor_sync(0xffffffffu, m, o));
            float sum = 0.f;
            #pragma unroll
            for (int i = 0; i < 4; i++){ x[i] = expf(x[i] - m); sum += x[i]; }
            #pragma unroll
            for (int o = 16; o; o >>= 1) sum += __shfl_xor_sync(0xffffffffu, sum, o);
            float inv = 1.f / sum;
            if (bl < BB && w == bl){
                #pragma unroll
                for (int i = 0; i < 4; i++)
                    out[OUT_ATT + ((size_t)s*BB + bl)*TT + lane + 32*i] = x[i] * inv;
            }
            float acc = 0.f;
            #pragma unroll
            for (int i = 0; i < 4; i++)
                acc += (x[i] * inv) * d_P[b][a][lane + 32*i];
            const double2* Wr = (const double2*)(W_av + (size_t)a*2*HH + HH);
            const double2* hv = (const double2*)(d_h[0][b]);
            unsigned long long a2 = 0ull;
            #pragma unroll
            for (int i = 0; i < 8; i++){
                int k4 = lane + 32*i;
                double2 wv = Wr[k4]; double2 h2 = hv[k4];
                a2 = fma2(wv.x, h2.x, a2);
                a2 = fma2(wv.y, h2.y, a2);
            }
            acc += upk(a2);
            acc = wred(acc);
            if (lane == 0) d_av1[b][a] = tanhf(acc + sm_bav[aq]);
        }
        gbar(bl, ++bgen);

        // ---- phase C: stage h/av to SMEM, stream W_cls double-buffered, argmax ----
        {
            for (int i = tid; i < BB*HH/4; i += NT)
                ((float4*)sm_hst)[i] = ((const float4*)(&d_h[0][0][0]))[i];
            for (int i = tid; i < BB*AA/4; i += NT)
                ((float4*)sm_avv)[i] = ((const float4*)(&d_av1[0][0]))[i];
            if (tid < 4) d_score_i[bl*4 + tid] = 0ull;
            __syncthreads();

            double2 rav[BB][4];
            #pragma unroll
            for (int b = 0; b < BB; b++)
                #pragma unroll
                for (int i = 0; i < 4; i++)
                    rav[b][i] = ((const double2*)(sm_avv + b*AA))[lane + 32*i];

            float bestv[BB] = {-3.4e38f,-3.4e38f,-3.4e38f,-3.4e38f};
            int   besti[BB] = {0,0,0,0};

            double2 wb[4];
            {
                const double2* W = (const double2*)(W_cls + (size_t)(base_v + w) * AA);
                #pragma unroll
                for (int i = 0; i < 4; i++) wb[i] = W[lane + 32*i];
            }
            for (int r = w; r < 125; r += 16){
                double2 wv[4];
                #pragma unroll
                for (int i = 0; i < 4; i++) wv[i] = wb[i];
                int rn = r + 16;
                if (rn < 125){
                    const double2* W2 = (const double2*)(W_cls + (size_t)(base_v + rn) * AA);
                    #pragma unroll
                    for (int i = 0; i < 4; i++) wb[i] = W2[lane + 32*i];
                }
                unsigned long long a2[BB] = {0ull,0ull,0ull,0ull};
                #pragma unroll
                for (int i = 0; i < 4; i++)
                    #pragma unroll
                    for (int b = 0; b < BB; b++){
                        a2[b] = fma2(wv[i].x, rav[b][i].x, a2[b]);
                        a2[b] = fma2(wv[i].y, rav[b][i].y, a2[b]);
                    }
                #pragma unroll
                for (int b = 0; b < BB; b++){
                    float lg = wred(upk(a2[b]));
                    if (lane == 0){
                        lg += sm_bcls[r];
                        sm_lg[b*125 + r] = lg;
                        if (lg > bestv[b]){ bestv[b] = lg; besti[b] = base_v + r; }
                    }
                }
            }
            if (lane == 0){
                #pragma unroll
                for (int b = 0; b < BB; b++){ sm_bv[w*BB + b] = bestv[b]; sm_bi[w*BB + b] = besti[b]; }
            }
            __syncthreads();
            for (int i = tid; i < BB*125; i += NT){
                int b = i / 125, r = i % 125;
                out[((size_t)s*BB + b)*VV + base_v + r] = sm_lg[i];
            }
            if (tid < BB){
                int b = tid;
                float best = -3.4e38f; int bi = 0;
                for (int w2 = 0; w2 < 16; w2++){
                    float v = sm_bv[w2*BB + b]; int i2 = sm_bi[w2*BB + b];
                    if (v > best || (v == best && i2 < bi)){ best = v; bi = i2; }
                }
                atomicMax(&d_best[cur][b], packbest(best, bi));
            }
        }
        gbar(bl, ++bgen);
    }
}

extern "C" void kernel_launch(void* const* d_in, const int* in_sizes, int n_in,
                              void* d_out, int out_size)
{
    (void)in_sizes; (void)n_in; (void)out_size;
    cudaFuncSetAttribute(seq2seq_kernel, cudaFuncAttributeMaxDynamicSharedMemorySize, DSMEM);
    seq2seq_kernel<<<NB, NT, DSMEM>>>(
        (const int*)  d_in[0],
        (const float*)d_in[1],  (const float*)d_in[2],  (const float*)d_in[3],
        (const float*)d_in[4],  (const float*)d_in[5],
        (const float*)d_in[6],  (const float*)d_in[7],  (const float*)d_in[8],
        (const float*)d_in[9],  (const float*)d_in[10],
        (const float*)d_in[11], (const float*)d_in[12],
        (const float*)d_in[13], (const float*)d_in[14],
        (float*)d_out);
}